// round 1
// baseline (speedup 1.0000x reference)
#include <cuda_runtime.h>
#include <cstdint>

// Problem constants (fixed by the reference).
#define BV 8192
#define GV 8
#define KV 1024
#define DV 64
#define KC 128            // codebook rows staged in smem per chunk

#define Q_ELEMS   ((size_t)BV * GV * DV)       // 4194304 quantized floats
#define IDX_OFF   Q_ELEMS                      // indices start
#define IDX_ELEMS ((size_t)BV * GV)            // 65536
#define SCL_OFF   (IDX_OFF + IDX_ELEMS)        // 4 scalars

// Scratch (no allocations allowed): histogram + commitment accumulator + c2 table.
__device__ int    g_hist[KV];
__device__ double g_commit;
__device__ float  g_c2[GV * KV];

// ---------------- packed f32x2 helpers (sm_100a) ----------------
static __device__ __forceinline__ unsigned long long ffma2(unsigned long long a,
                                                           unsigned long long b,
                                                           unsigned long long c) {
    unsigned long long d;
    asm("fma.rn.f32x2 %0, %1, %2, %3;" : "=l"(d) : "l"(a), "l"(b), "l"(c));
    return d;
}
static __device__ __forceinline__ unsigned long long fadd2(unsigned long long a,
                                                           unsigned long long b) {
    unsigned long long d;
    asm("add.rn.f32x2 %0, %1, %2;" : "=l"(d) : "l"(a), "l"(b));
    return d;
}
static __device__ __forceinline__ float2 unpack2(unsigned long long p) {
    float2 r;
    asm("mov.b64 {%0, %1}, %2;" : "=f"(r.x), "=f"(r.y) : "l"(p));
    return r;
}

// ---------------- init: zero scratch (runs every launch; graph-replay safe) ----
__global__ void vq_init_kernel() {
    int t = threadIdx.x;
    if (t < KV) g_hist[t] = 0;
    if (t == 0) g_commit = 0.0;
}

// ---------------- c2[g][k] = sum_d codebook[g][k][d]^2 ----------------
__global__ void vq_c2_kernel(const float* __restrict__ cb) {
    int i = blockIdx.x * blockDim.x + threadIdx.x;   // 0 .. G*K-1
    if (i >= GV * KV) return;
    const float* p = cb + (size_t)i * DV;
    float s = 0.0f;
#pragma unroll
    for (int d = 0; d < DV; d++) s = fmaf(p[d], p[d], s);
    g_c2[i] = s;
}

// ---------------- main: argmin + quantized copy + partial reductions ----------
__global__ void __launch_bounds__(256, 2)
vq_main_kernel(const float* __restrict__ z,
               const float* __restrict__ cb,
               float* __restrict__ out) {
    __shared__ __align__(16) float cs[KC * DV];   // 32 KB codebook chunk
    __shared__ float sc2[KC];

    const int tid = threadIdx.x;
    const int b   = blockIdx.x * 256 + tid;       // one row per thread
    const int g   = blockIdx.y;

    const float* zrow = z + (size_t)b * (GV * DV) + (size_t)g * DV;
    const float* cbg  = cb + (size_t)g * KV * DV;

    // Load this thread's z vector, packed as 32 x f32x2 in registers.
    unsigned long long zq[32];
    {
        const ulonglong2* zp = (const ulonglong2*)zrow;
#pragma unroll
        for (int i = 0; i < 16; i++) {
            ulonglong2 v = zp[i];
            zq[2 * i]     = v.x;
            zq[2 * i + 1] = v.y;
        }
    }

    // z2 = sum z^2 (constant across k for this row).
    float z2;
    {
        unsigned long long a0 = 0ull, a1 = 0ull, a2 = 0ull, a3 = 0ull;
#pragma unroll
        for (int i = 0; i < 32; i += 4) {
            a0 = ffma2(zq[i + 0], zq[i + 0], a0);
            a1 = ffma2(zq[i + 1], zq[i + 1], a1);
            a2 = ffma2(zq[i + 2], zq[i + 2], a2);
            a3 = ffma2(zq[i + 3], zq[i + 3], a3);
        }
        float2 s = unpack2(fadd2(fadd2(a0, a1), fadd2(a2, a3)));
        z2 = s.x + s.y;
    }

    float best  = 3.402823466e38f;
    int   bestk = 0;

    for (int k0 = 0; k0 < KV; k0 += KC) {
        __syncthreads();   // protect smem reuse across chunks
        // Cooperative load of 128 codewords (8192 floats) + their c2.
        {
            const float4* src = (const float4*)(cbg + (size_t)k0 * DV);
            float4* dst = (float4*)cs;
#pragma unroll
            for (int i = 0; i < 8; i++) dst[tid + 256 * i] = src[tid + 256 * i];
            if (tid < KC) sc2[tid] = g_c2[g * KV + k0 + tid];
        }
        __syncthreads();

#pragma unroll 2
        for (int k = 0; k < KC; k++) {
            const ulonglong2* c = (const ulonglong2*)(cs + k * DV);
            unsigned long long b0 = 0ull, b1 = 0ull, b2 = 0ull, b3 = 0ull;
#pragma unroll
            for (int i = 0; i < 16; i++) {
                ulonglong2 cv = c[i];       // broadcast LDS.128, conflict-free
                if ((i & 1) == 0) {
                    b0 = ffma2(zq[2 * i],     cv.x, b0);
                    b1 = ffma2(zq[2 * i + 1], cv.y, b1);
                } else {
                    b2 = ffma2(zq[2 * i],     cv.x, b2);
                    b3 = ffma2(zq[2 * i + 1], cv.y, b3);
                }
            }
            float2 s = unpack2(fadd2(fadd2(b0, b1), fadd2(b2, b3)));
            float dot = s.x + s.y;
            // Replicate reference rounding: t = z2 + c2; dist = t - 2*zc.
            float t    = z2 + sc2[k];
            float dist = t - 2.0f * dot;
            if (dist < best) { best = dist; bestk = k0 + k; }   // first-index ties
        }
    }

    // ---- epilogue ----
    // index output (as float; 0..1023 exact)
    out[IDX_OFF + (size_t)b * GV + g] = (float)bestk;
    atomicAdd(&g_hist[bestk], 1);

    // quantized = exact codebook row; commitment partial = sum (z - q)^2
    const float4* q4 = (const float4*)(cbg + (size_t)bestk * DV);
    float4* o4 = (float4*)(out + (size_t)b * (GV * DV) + (size_t)g * DV);
    float csum = 0.0f;
#pragma unroll
    for (int i = 0; i < 16; i++) {
        float4 q = q4[i];
        o4[i] = q;
        float2 zlo = unpack2(zq[2 * i]);
        float2 zhi = unpack2(zq[2 * i + 1]);
        float d0 = zlo.x - q.x, d1 = zlo.y - q.y;
        float d2 = zhi.x - q.z, d3 = zhi.y - q.w;
        csum += d0 * d0 + d1 * d1 + d2 * d2 + d3 * d3;
    }
    // warp-reduce then one double atomic per warp
#pragma unroll
    for (int o = 16; o > 0; o >>= 1)
        csum += __shfl_down_sync(0xffffffffu, csum, o);
    if ((tid & 31) == 0) atomicAdd(&g_commit, (double)csum);
}

// ---------------- final: entropy / perplexity / losses ----------------
__global__ void vq_final_kernel(float* __restrict__ out) {
    __shared__ float red[1024];
    int t = threadIdx.x;
    float u    = (float)g_hist[t] * (1.0f / (float)(BV * GV));
    float term = -u * logf(u + 1e-10f);
    red[t] = term;
    __syncthreads();
    for (int s = 512; s > 0; s >>= 1) {
        if (t < s) red[t] += red[t + s];
        __syncthreads();
    }
    if (t == 0) {
        float ent = red[0];
        out[SCL_OFF + 0] = (float)(g_commit / (double)Q_ELEMS);  // commitment_loss
        out[SCL_OFF + 1] = 0.0f;                                 // codebook_loss
        out[SCL_OFF + 2] = ent;                                  // entropy
        out[SCL_OFF + 3] = expf(ent);                            // perplexity
    }
}

extern "C" void kernel_launch(void* const* d_in, const int* in_sizes, int n_in,
                              void* d_out, int out_size) {
    // Identify inputs by size (z: 4194304, codebook: 524288) — robust to order.
    const float* z  = (const float*)d_in[0];
    const float* cb = (const float*)d_in[1];
    if (n_in >= 2 && in_sizes[0] == GV * KV * DV) {
        cb = (const float*)d_in[0];
        z  = (const float*)d_in[1];
    }
    float* out = (float*)d_out;

    vq_init_kernel<<<1, 1024>>>();
    vq_c2_kernel<<<(GV * KV + 1023) / 1024, 1024>>>(cb);
    dim3 grid(BV / 256, GV);
    vq_main_kernel<<<grid, 256>>>(z, cb, out);
    vq_final_kernel<<<1, 1024>>>(out);
}

// round 3
// speedup vs baseline: 1.0518x; 1.0518x over previous
#include <cuda_runtime.h>
#include <cstdint>

// Problem constants (fixed by the reference).
#define BV 8192
#define GV 8
#define KV 1024
#define DV 64

#define Q_ELEMS   ((size_t)BV * GV * DV)       // 4194304 quantized floats
#define IDX_OFF   Q_ELEMS                      // indices start
#define IDX_ELEMS ((size_t)BV * GV)            // 65536
#define SCL_OFF   (IDX_OFF + IDX_ELEMS)        // 4 scalars

// Scratch (no allocations allowed).
__device__ int    g_hist[KV];
__device__ double g_commit;
__device__ float  g_c2[GV * KV];

// ---------------- packed f32x2 helpers ----------------
static __device__ __forceinline__ unsigned long long ffma2(unsigned long long a,
                                                           unsigned long long b,
                                                           unsigned long long c) {
    unsigned long long d;
    asm("fma.rn.f32x2 %0, %1, %2, %3;" : "=l"(d) : "l"(a), "l"(b), "l"(c));
    return d;
}
static __device__ __forceinline__ float2 unpack2(unsigned long long p) {
    float2 r;
    asm("mov.b64 {%0, %1}, %2;" : "=f"(r.x), "=f"(r.y) : "l"(p));
    return r;
}

// ---------------- cp.async helpers ----------------
static __device__ __forceinline__ void cp_async16(uint32_t dst, const void* src) {
    asm volatile("cp.async.cg.shared.global [%0], [%1], 16;" :: "r"(dst), "l"(src));
}
static __device__ __forceinline__ void cp_commit() {
    asm volatile("cp.async.commit_group;");
}
template <int N> static __device__ __forceinline__ void cp_wait() {
    asm volatile("cp.async.wait_group %0;" :: "n"(N));
}

// XOR swizzle on 16-byte units: row r, unit u -> float offset.
#define SWZ(r, u) (((r) << 6) + ((((u) ^ ((r) & 15))) << 2))

// ---------------- init ----------------
__global__ void vq_init_kernel() {
    int t = threadIdx.x;
    if (t < KV) g_hist[t] = 0;
    if (t == 0) g_commit = 0.0;
}

// ---------------- c2[g][k] ----------------
__global__ void vq_c2_kernel(const float* __restrict__ cb) {
    int i = blockIdx.x * blockDim.x + threadIdx.x;
    if (i >= GV * KV) return;
    const float* p = cb + (size_t)i * DV;
    float s = 0.0f;
#pragma unroll
    for (int d = 0; d < DV; d++) s = fmaf(p[d], p[d], s);
    g_c2[i] = s;
}

// no-op padding kernels so ncu's (-s 5 -c 1) lands on vq_main_kernel
__global__ void vq_nop_kernel() {}

// ---------------- main: 64-row x full-K block, 4x4 register tiling ----------
__global__ void __launch_bounds__(256, 3)
vq_main_kernel(const float* __restrict__ z,
               const float* __restrict__ cb,
               float* __restrict__ out) {
    __shared__ __align__(16) float zs[64 * 64];        // 16 KB, swizzled
    __shared__ __align__(16) float cbs[2][64 * 64];    // 32 KB, double-buffered, swizzled

    const int tid  = threadIdx.x;
    const int tx   = tid & 15;    // k-group: ks = tx + 16*j
    const int ty   = tid >> 4;    // row-group: rows = ty*4 + j
    const int g    = blockIdx.y;
    const int row0 = blockIdx.x * 64;

    const float* cbg = cb + (size_t)g * (KV * DV);

    uint32_t zs_a  = (uint32_t)__cvta_generic_to_shared(zs);
    uint32_t cbs_a = (uint32_t)__cvta_generic_to_shared(cbs);

    // --- issue z tile load (group A) ---
#pragma unroll
    for (int it = 0; it < 4; it++) {
        int i = tid + 256 * it;           // 1024 16B units
        int r = i >> 4, u = i & 15;
        const float* src = z + (size_t)(row0 + r) * (GV * DV) + (size_t)g * DV + (u << 2);
        cp_async16(zs_a + SWZ(r, u) * 4, src);
    }
    cp_commit();

    // --- issue codebook chunk 0 (group B) ---
#pragma unroll
    for (int it = 0; it < 4; it++) {
        int i = tid + 256 * it;
        int k = i >> 4, u = i & 15;
        cp_async16(cbs_a + SWZ(k, u) * 4, cbg + (size_t)i * 4);
    }
    cp_commit();

    cp_wait<1>();            // z tile arrived
    __syncthreads();

    // z2 for this thread's 4 rows
    float z2v[4];
#pragma unroll
    for (int j = 0; j < 4; j++) {
        int r = ty * 4 + j;
        float s = 0.0f;
#pragma unroll
        for (int u = 0; u < 16; u++) {
            float4 v = *(const float4*)&zs[SWZ(r, u)];
            s = fmaf(v.x, v.x, fmaf(v.y, v.y, fmaf(v.z, v.z, fmaf(v.w, v.w, s))));
        }
        z2v[j] = s;
    }

    float best[4]  = {3.402823466e38f, 3.402823466e38f, 3.402823466e38f, 3.402823466e38f};
    int   bestk[4] = {0, 0, 0, 0};

    int buf = 0;
    for (int c = 0; c < 16; c++) {
        if (c < 15) {
            const float* src0 = cbg + (size_t)(c + 1) * (64 * 64);
            uint32_t dst0 = cbs_a + (uint32_t)(buf ^ 1) * (64 * 64 * 4);
#pragma unroll
            for (int it = 0; it < 4; it++) {
                int i = tid + 256 * it;
                int k = i >> 4, u = i & 15;
                cp_async16(dst0 + SWZ(k, u) * 4, src0 + (size_t)i * 4);
            }
            cp_commit();
            cp_wait<1>();    // chunk c arrived
        } else {
            cp_wait<0>();
        }
        __syncthreads();

        const float* cbf = cbs[buf];
        unsigned long long acc[4][4];
#pragma unroll
        for (int r = 0; r < 4; r++)
#pragma unroll
            for (int kk = 0; kk < 4; kk++) acc[r][kk] = 0ull;

#pragma unroll 4
        for (int dg = 0; dg < 16; dg++) {
            ulonglong2 zf[4], cf[4];
#pragma unroll
            for (int j = 0; j < 4; j++)
                zf[j] = *(const ulonglong2*)&zs[SWZ(ty * 4 + j, dg)];
#pragma unroll
            for (int j = 0; j < 4; j++)
                cf[j] = *(const ulonglong2*)&cbf[SWZ(tx + 16 * j, dg)];
#pragma unroll
            for (int r = 0; r < 4; r++)
#pragma unroll
                for (int kk = 0; kk < 4; kk++) {
                    acc[r][kk] = ffma2(zf[r].x, cf[kk].x, acc[r][kk]);
                    acc[r][kk] = ffma2(zf[r].y, cf[kk].y, acc[r][kk]);
                }
        }

        // dist epilogue for this chunk (ascending k within thread -> first-index ties)
#pragma unroll
        for (int kk = 0; kk < 4; kk++) {
            int kg = c * 64 + tx + 16 * kk;
            float c2 = __ldg(&g_c2[g * KV + kg]);
#pragma unroll
            for (int r = 0; r < 4; r++) {
                float2 s   = unpack2(acc[r][kk]);
                float  dot = s.x + s.y;
                float  t    = z2v[r] + c2;           // reference rounding order
                float  dist = t - 2.0f * dot;
                if (dist < best[r]) { best[r] = dist; bestk[r] = kg; }
            }
        }
        __syncthreads();     // protect buf^1 before next iteration's cp.async overwrite
        buf ^= 1;
    }

    // ---- cross-thread argmin reduction (alias dead codebook smem) ----
    float* sd = cbs[0];                 // 64*16 floats
    int*   sk = (int*)cbs[1];           // 64*16 ints
#pragma unroll
    for (int j = 0; j < 4; j++) {
        int r = ty * 4 + j;
        sd[r * 16 + tx] = best[j];
        sk[r * 16 + tx] = bestk[j];
    }
    __syncthreads();

    if (tid < 64) {
        int   r  = tid;
        float bd = sd[r * 16];
        int   bk = sk[r * 16];
#pragma unroll
        for (int t = 1; t < 16; t++) {
            float d = sd[r * 16 + t];
            int   k = sk[r * 16 + t];
            if (d < bd || (d == bd && k < bk)) { bd = d; bk = k; }
        }

        size_t brow = (size_t)(row0 + r);
        out[IDX_OFF + brow * GV + g] = (float)bk;
        atomicAdd(&g_hist[bk], 1);

        const float4* q4 = (const float4*)(cbg + (size_t)bk * DV);
        float4* o4 = (float4*)(out + brow * (GV * DV) + (size_t)g * DV);
        float csum = 0.0f;
#pragma unroll
        for (int u = 0; u < 16; u++) {
            float4 q = q4[u];
            o4[u] = q;
            float4 zv = *(const float4*)&zs[SWZ(r, u)];
            float d0 = zv.x - q.x, d1 = zv.y - q.y;
            float d2 = zv.z - q.z, d3 = zv.w - q.w;
            csum += d0 * d0 + d1 * d1 + d2 * d2 + d3 * d3;
        }
#pragma unroll
        for (int o = 16; o > 0; o >>= 1)
            csum += __shfl_down_sync(0xffffffffu, csum, o);
        if ((tid & 31) == 0) atomicAdd(&g_commit, (double)csum);
    }
}

// ---------------- final: entropy / perplexity / losses ----------------
__global__ void vq_final_kernel(float* __restrict__ out) {
    __shared__ float red[1024];
    int t = threadIdx.x;
    float u    = (float)g_hist[t] * (1.0f / (float)(BV * GV));
    float term = -u * logf(u + 1e-10f);
    red[t] = term;
    __syncthreads();
    for (int s = 512; s > 0; s >>= 1) {
        if (t < s) red[t] += red[t + s];
        __syncthreads();
    }
    if (t == 0) {
        float ent = red[0];
        out[SCL_OFF + 0] = (float)(g_commit / (double)Q_ELEMS);  // commitment_loss
        out[SCL_OFF + 1] = 0.0f;                                 // codebook_loss
        out[SCL_OFF + 2] = ent;                                  // entropy
        out[SCL_OFF + 3] = expf(ent);                            // perplexity
    }
}

extern "C" void kernel_launch(void* const* d_in, const int* in_sizes, int n_in,
                              void* d_out, int out_size) {
    const float* z  = (const float*)d_in[0];
    const float* cb = (const float*)d_in[1];
    if (n_in >= 2 && in_sizes[0] == GV * KV * DV) {
        cb = (const float*)d_in[0];
        z  = (const float*)d_in[1];
    }
    float* out = (float*)d_out;

    vq_init_kernel<<<1, 1024>>>();                          // launch 0
    vq_c2_kernel<<<(GV * KV + 1023) / 1024, 1024>>>(cb);    // launch 1
    vq_nop_kernel<<<1, 32>>>();                             // launch 2
    vq_nop_kernel<<<1, 32>>>();                             // launch 3
    vq_nop_kernel<<<1, 32>>>();                             // launch 4
    dim3 grid(BV / 64, GV);
    vq_main_kernel<<<grid, 256>>>(z, cb, out);              // launch 5 <- ncu -s 5 -c 1
    vq_final_kernel<<<1, 1024>>>(out);                      // launch 6
}

// round 6
// speedup vs baseline: 1.5241x; 1.4491x over previous
#include <cuda_runtime.h>
#include <cuda_bf16.h>
#include <cstdint>

// Problem constants (fixed by the reference).
#define BV 8192
#define GV 8
#define KV 1024
#define DV 64

#define Q_ELEMS   ((size_t)BV * GV * DV)       // 4194304 quantized floats
#define IDX_OFF   Q_ELEMS
#define IDX_ELEMS ((size_t)BV * GV)            // 65536
#define SCL_OFF   (IDX_OFF + IDX_ELEMS)
#define C_ELEMS   ((size_t)GV * KV * DV)       // 524288

// Scratch (static __device__ globals; no allocations allowed).
__device__ int      g_hist[KV];
__device__ double   g_commit;
__device__ float    g_c2[GV * KV];
__device__ uint16_t g_zh[Q_ELEMS], g_zm[Q_ELEMS], g_zl[Q_ELEMS];   // z bf16 planes
__device__ uint16_t g_ch[C_ELEMS], g_cm[C_ELEMS], g_cl[C_ELEMS];   // codebook planes

// ---------------- PTX helpers (all sm_80-class, safe for compute_100) --------
static __device__ __forceinline__ void cp_async16(uint32_t dst, const void* src) {
    asm volatile("cp.async.cg.shared.global [%0], [%1], 16;" :: "r"(dst), "l"(src));
}
static __device__ __forceinline__ void cp_commit() {
    asm volatile("cp.async.commit_group;");
}
template <int N> static __device__ __forceinline__ void cp_wait() {
    asm volatile("cp.async.wait_group %0;" :: "n"(N));
}

#define LDSM_X4(R, addr) \
    asm volatile("ldmatrix.sync.aligned.m8n8.x4.shared.b16 {%0,%1,%2,%3}, [%4];" \
        : "=r"((R)[0]), "=r"((R)[1]), "=r"((R)[2]), "=r"((R)[3]) : "r"(addr))

#define MMA16816(C, A, b0_, b1_) \
    asm volatile("mma.sync.aligned.m16n8k16.row.col.f32.bf16.bf16.f32 " \
        "{%0,%1,%2,%3}, {%4,%5,%6,%7}, {%8,%9}, {%0,%1,%2,%3};" \
        : "+f"((C)[0]), "+f"((C)[1]), "+f"((C)[2]), "+f"((C)[3]) \
        : "r"((A)[0]), "r"((A)[1]), "r"((A)[2]), "r"((A)[3]), "r"(b0_), "r"(b1_))

// Dynamic smem layout.
#define OFF_C2 0                     // 1024 floats = 4096 B
#define OFF_Z2 4096                  // 128 floats
#define OFF_BK 4608                  // 128 ints
#define OFF_A  8192                  // 3 planes x 16384 B (128 rows x 128 B, swizzled)
#define OFF_B  (OFF_A + 3 * 16384)   // 57344; 3 planes x 16384 B
#define SMEM_TOTAL (OFF_B + 3 * 16384)   // 106496 B

// ---------------- small kernels ----------------
__global__ void vq_init_kernel() {
    int t = threadIdx.x;
    if (t < KV) g_hist[t] = 0;
    if (t == 0) g_commit = 0.0;
}

__global__ void vq_c2_kernel(const float* __restrict__ cb) {
    int i = blockIdx.x * blockDim.x + threadIdx.x;
    if (i >= GV * KV) return;
    const float* p = cb + (size_t)i * DV;
    float s = 0.0f;
#pragma unroll
    for (int d = 0; d < DV; d++) s = fmaf(p[d], p[d], s);
    g_c2[i] = s;
}

static __device__ __forceinline__ void split3(float x, uint16_t& h, uint16_t& m, uint16_t& l) {
    __nv_bfloat16 bh = __float2bfloat16_rn(x);
    float r1 = x - __bfloat162float(bh);
    __nv_bfloat16 bm = __float2bfloat16_rn(r1);
    float r2 = r1 - __bfloat162float(bm);
    __nv_bfloat16 bl = __float2bfloat16_rn(r2);
    h = __bfloat16_as_ushort(bh);
    m = __bfloat16_as_ushort(bm);
    l = __bfloat16_as_ushort(bl);
}

__global__ void vq_split_z_kernel(const float* __restrict__ z) {
    size_t i = (size_t)blockIdx.x * blockDim.x + threadIdx.x;
    if (i >= Q_ELEMS) return;
    split3(z[i], g_zh[i], g_zm[i], g_zl[i]);
}
__global__ void vq_split_cb_kernel(const float* __restrict__ cb) {
    size_t i = (size_t)blockIdx.x * blockDim.x + threadIdx.x;
    if (i >= C_ELEMS) return;
    split3(cb[i], g_ch[i], g_cm[i], g_cl[i]);
}

// ---------------- main: mma.sync bf16x3 GEMM + fused argmin ----------------
// Block: 128 rows x one group, 256 threads = 8 warps; warp w owns rows
// [w*16, w*16+16). Codebook processed in 8 panels of 128 codewords; per panel
// 8 iterations of n16. 6 plane-products (hh,hm,mh,mm,hl,lh) accumulate the
// fp32 dot in tensor-core C fragments.
__global__ void __launch_bounds__(256, 2)
vq_mma_kernel(const float* __restrict__ z,
              const float* __restrict__ cb,
              float* __restrict__ out) {
    extern __shared__ __align__(1024) char smem[];
    const int tid = threadIdx.x;
    const int w = tid >> 5, t = tid & 31;
    const int g = blockIdx.y;
    const int row0 = blockIdx.x * 128;

    uint32_t sb = (uint32_t)__cvta_generic_to_shared(smem);
    float* c2s = (float*)(smem + OFF_C2);
    float* z2s = (float*)(smem + OFF_Z2);
    int*   bks = (int*)(smem + OFF_BK);

    const uint16_t* zpl[3] = {g_zh, g_zm, g_zl};
    const uint16_t* cpl[3] = {g_ch, g_cm, g_cl};

    // Stage c2 row for this group (1024 floats).
    *(float4*)&c2s[tid * 4] = *(const float4*)&g_c2[g * KV + tid * 4];

    // A tile: 3 planes x 128 rows x 64 bf16 (128 B rows), XOR swizzle on 16B units.
#pragma unroll
    for (int it = 0; it < 12; it++) {
        int i = tid + 256 * it;
        int p = i >> 10, j = i & 1023, r = j >> 3, u = j & 7;
        const uint16_t* src = zpl[p] + (size_t)(row0 + r) * (GV * DV) + (size_t)g * DV + u * 8;
        cp_async16(sb + OFF_A + p * 16384 + r * 128 + ((u ^ (r & 7)) << 4), src);
    }
    cp_commit();

    // z2 per row (fp32 from original z).
    if (tid < 128) {
        const float* zr = z + (size_t)(row0 + tid) * (GV * DV) + (size_t)g * DV;
        float s = 0.0f;
#pragma unroll
        for (int d = 0; d < DV; d++) s = fmaf(zr[d], zr[d], s);
        z2s[tid] = s;
    }

    // B panel 0.
#pragma unroll
    for (int it = 0; it < 12; it++) {
        int i = tid + 256 * it;
        int p = i >> 10, j = i & 1023, r = j >> 3, u = j & 7;
        const uint16_t* src = cpl[p] + (size_t)g * (KV * DV) + (size_t)r * DV + u * 8;
        cp_async16(sb + OFF_B + p * 16384 + r * 128 + ((u ^ (r & 7)) << 4), src);
    }
    cp_commit();
    cp_wait<0>();
    __syncthreads();

    // A fragments: af[plane][kstep][4]. ldmatrix x4 lane-address mapping:
    //  t0-7:[m0-7,klo] t8-15:[m8-15,klo] t16-23:[m0-7,khi] t24-31:[m8-15,khi]
    uint32_t af[3][4][4];
    {
        int rowoff = (t & 7) + ((t >> 3) & 1) * 8;
        int m = w * 16 + rowoff;
        int ub = (t >> 4) & 1;
#pragma unroll
        for (int p = 0; p < 3; p++)
#pragma unroll
            for (int ks = 0; ks < 4; ks++) {
                int u = ks * 2 + ub;
                uint32_t addr = sb + OFF_A + p * 16384 + m * 128 + ((u ^ (rowoff & 7)) << 4);
                LDSM_X4(af[p][ks], addr);
            }
    }

    float z2lo = z2s[w * 16 + (t >> 2)];
    float z2hi = z2s[w * 16 + (t >> 2) + 8];
    float bestlo = 3.402823466e38f, besthi = 3.402823466e38f;
    int   klo = 0, khi = 0;

    // B ldmatrix lane mapping: t0-7:[n0-7,klo] t8-15:[n0-7,khi]
    //                          t16-23:[n8-15,klo] t24-31:[n8-15,khi]
    const int browoff = (t & 7) + ((t >> 4) & 1) * 8;
    const int bub = (t >> 3) & 1;
    const int j2 = (t & 3) * 2;

    for (int panel = 0; panel < 8; panel++) {
        if (panel > 0) {
#pragma unroll
            for (int it = 0; it < 12; it++) {
                int i = tid + 256 * it;
                int p = i >> 10, j = i & 1023, r = j >> 3, u = j & 7;
                const uint16_t* src = cpl[p] + (size_t)g * (KV * DV)
                                     + (size_t)(panel * 128 + r) * DV + u * 8;
                cp_async16(sb + OFF_B + p * 16384 + r * 128 + ((u ^ (r & 7)) << 4), src);
            }
            cp_commit();
            cp_wait<0>();
            __syncthreads();
        }

#pragma unroll 1
        for (int itn = 0; itn < 8; itn++) {
            float cA[4] = {0.f, 0.f, 0.f, 0.f};
            float cB[4] = {0.f, 0.f, 0.f, 0.f};
            int nloc = itn * 16;
            int br = nloc + browoff;
            uint32_t baddr0 = sb + OFF_B + br * 128;
#pragma unroll
            for (int ks = 0; ks < 4; ks++) {
                uint32_t bb[3][4];
                int u = ks * 2 + bub;
                uint32_t sw = (uint32_t)((u ^ (br & 7)) << 4);
#pragma unroll
                for (int p = 0; p < 3; p++)
                    LDSM_X4(bb[p], baddr0 + p * 16384 + sw);
                // 6 plane products, both n8-tiles each.
                MMA16816(cA, af[0][ks], bb[0][0], bb[0][1]);
                MMA16816(cB, af[0][ks], bb[0][2], bb[0][3]);
                MMA16816(cA, af[0][ks], bb[1][0], bb[1][1]);
                MMA16816(cB, af[0][ks], bb[1][2], bb[1][3]);
                MMA16816(cA, af[1][ks], bb[0][0], bb[0][1]);
                MMA16816(cB, af[1][ks], bb[0][2], bb[0][3]);
                MMA16816(cA, af[1][ks], bb[1][0], bb[1][1]);
                MMA16816(cB, af[1][ks], bb[1][2], bb[1][3]);
                MMA16816(cA, af[0][ks], bb[2][0], bb[2][1]);
                MMA16816(cB, af[0][ks], bb[2][2], bb[2][3]);
                MMA16816(cA, af[2][ks], bb[0][0], bb[0][1]);
                MMA16816(cB, af[2][ks], bb[0][2], bb[0][3]);
            }
            // dist epilogue, reference rounding: fma(-2, dot, fp32(z2 + c2)).
            int kbase = panel * 128 + nloc;
            float2 p0 = *(const float2*)&c2s[kbase + j2];
            float2 p1 = *(const float2*)&c2s[kbase + 8 + j2];
            float d;
            d = fmaf(-2.0f, cA[0], z2lo + p0.x); if (d < bestlo) { bestlo = d; klo = kbase + j2; }
            d = fmaf(-2.0f, cA[1], z2lo + p0.y); if (d < bestlo) { bestlo = d; klo = kbase + j2 + 1; }
            d = fmaf(-2.0f, cB[0], z2lo + p1.x); if (d < bestlo) { bestlo = d; klo = kbase + 8 + j2; }
            d = fmaf(-2.0f, cB[1], z2lo + p1.y); if (d < bestlo) { bestlo = d; klo = kbase + 8 + j2 + 1; }
            d = fmaf(-2.0f, cA[2], z2hi + p0.x); if (d < besthi) { besthi = d; khi = kbase + j2; }
            d = fmaf(-2.0f, cA[3], z2hi + p0.y); if (d < besthi) { besthi = d; khi = kbase + j2 + 1; }
            d = fmaf(-2.0f, cB[2], z2hi + p1.x); if (d < besthi) { besthi = d; khi = kbase + 8 + j2; }
            d = fmaf(-2.0f, cB[3], z2hi + p1.y); if (d < besthi) { besthi = d; khi = kbase + 8 + j2 + 1; }
        }
        __syncthreads();   // everyone done reading B before next panel overwrite
    }

    // Cross-lane argmin within each quad (lexicographic: dist, then smaller k).
#pragma unroll
    for (int off = 1; off <= 2; off <<= 1) {
        float d2 = __shfl_xor_sync(0xffffffffu, bestlo, off);
        int   k2 = __shfl_xor_sync(0xffffffffu, klo, off);
        if (d2 < bestlo || (d2 == bestlo && k2 < klo)) { bestlo = d2; klo = k2; }
        d2 = __shfl_xor_sync(0xffffffffu, besthi, off);
        k2 = __shfl_xor_sync(0xffffffffu, khi, off);
        if (d2 < besthi || (d2 == besthi && k2 < khi)) { besthi = d2; khi = k2; }
    }
    if ((t & 3) == 0) {
        bks[w * 16 + (t >> 2)] = klo;
        bks[w * 16 + (t >> 2) + 8] = khi;
    }
    __syncthreads();

    // Cooperative output: thread handles half a row (32 floats).
    {
        int r = tid >> 1, half = tid & 1;
        int bk = bks[r];
        size_t brow = (size_t)(row0 + r);
        if (!half) {
            out[IDX_OFF + brow * GV + g] = (float)bk;
            atomicAdd(&g_hist[bk], 1);
        }
        const float4* q4 = (const float4*)(cb + (size_t)g * (KV * DV) + (size_t)bk * DV) + half * 8;
        const float4* z4 = (const float4*)(z + brow * (GV * DV) + (size_t)g * DV) + half * 8;
        float4* o4 = (float4*)(out + brow * (GV * DV) + (size_t)g * DV) + half * 8;
        float csum = 0.0f;
#pragma unroll
        for (int u = 0; u < 8; u++) {
            float4 q = q4[u], zv = z4[u];
            o4[u] = q;
            float d0 = zv.x - q.x, d1 = zv.y - q.y;
            float d2 = zv.z - q.z, d3 = zv.w - q.w;
            csum += d0 * d0 + d1 * d1 + d2 * d2 + d3 * d3;
        }
#pragma unroll
        for (int off = 16; off > 0; off >>= 1)
            csum += __shfl_down_sync(0xffffffffu, csum, off);
        float* red = z2s;   // z2s is dead past this barrier-separated point
        if (t == 0) red[w] = csum;
        __syncthreads();
        if (tid == 0) {
            float s = 0.0f;
#pragma unroll
            for (int i = 0; i < 8; i++) s += red[i];
            atomicAdd(&g_commit, (double)s);
        }
    }
}

// ---------------- final: entropy / perplexity / losses ----------------
__global__ void vq_final_kernel(float* __restrict__ out) {
    __shared__ float red[1024];
    int t = threadIdx.x;
    float u    = (float)g_hist[t] * (1.0f / (float)(BV * GV));
    float term = -u * logf(u + 1e-10f);
    red[t] = term;
    __syncthreads();
    for (int s = 512; s > 0; s >>= 1) {
        if (t < s) red[t] += red[t + s];
        __syncthreads();
    }
    if (t == 0) {
        float ent = red[0];
        out[SCL_OFF + 0] = (float)(g_commit / (double)Q_ELEMS);
        out[SCL_OFF + 1] = 0.0f;
        out[SCL_OFF + 2] = ent;
        out[SCL_OFF + 3] = expf(ent);
    }
}

extern "C" void kernel_launch(void* const* d_in, const int* in_sizes, int n_in,
                              void* d_out, int out_size) {
    const float* z  = (const float*)d_in[0];
    const float* cb = (const float*)d_in[1];
    if (n_in >= 2 && in_sizes[0] == GV * KV * DV) {
        cb = (const float*)d_in[0];
        z  = (const float*)d_in[1];
    }
    float* out = (float*)d_out;

    cudaFuncSetAttribute(vq_mma_kernel, cudaFuncAttributeMaxDynamicSharedMemorySize, SMEM_TOTAL);

    vq_init_kernel<<<1, 1024>>>();                                      // launch 1
    vq_split_z_kernel<<<(int)((Q_ELEMS + 255) / 256), 256>>>(z);        // launch 2
    vq_split_cb_kernel<<<(int)((C_ELEMS + 255) / 256), 256>>>(cb);      // launch 3
    vq_c2_kernel<<<(GV * KV + 1023) / 1024, 1024>>>(cb);                // launch 4
    dim3 grid(BV / 128, GV);
    vq_mma_kernel<<<grid, 256, SMEM_TOTAL>>>(z, cb, out);               // launch 5 <- ncu
    vq_final_kernel<<<1, 1024>>>(out);                                  // launch 6
}

// round 10
// speedup vs baseline: 2.0980x; 1.3766x over previous
#include <cuda_runtime.h>
#include <cuda_bf16.h>
#include <cstdint>

// Problem constants (fixed by the reference).
#define BV 8192
#define GV 8
#define KV 1024
#define DV 64

#define Q_ELEMS   ((size_t)BV * GV * DV)       // 4194304 quantized floats
#define IDX_OFF   Q_ELEMS
#define IDX_ELEMS ((size_t)BV * GV)            // 65536
#define SCL_OFF   (IDX_OFF + IDX_ELEMS)
#define C_ELEMS   ((size_t)GV * KV * DV)       // 524288

// Scratch (static __device__ globals; no allocations allowed).
__device__ int      g_hist[KV];
__device__ double   g_commit;
__device__ float    g_c2[GV * KV];
__device__ uint16_t g_ch[C_ELEMS], g_cm[C_ELEMS], g_cl[C_ELEMS];   // codebook planes

// ---------------- PTX helpers (sm_80-class, safe for compute_100) --------
static __device__ __forceinline__ void cp_async16(uint32_t dst, const void* src) {
    asm volatile("cp.async.cg.shared.global [%0], [%1], 16;" :: "r"(dst), "l"(src));
}
static __device__ __forceinline__ void cp_commit() {
    asm volatile("cp.async.commit_group;");
}
template <int N> static __device__ __forceinline__ void cp_wait() {
    asm volatile("cp.async.wait_group %0;" :: "n"(N));
}

#define LDSM_X4(R, addr) \
    asm volatile("ldmatrix.sync.aligned.m8n8.x4.shared.b16 {%0,%1,%2,%3}, [%4];" \
        : "=r"((R)[0]), "=r"((R)[1]), "=r"((R)[2]), "=r"((R)[3]) : "r"(addr))

#define MMA16816(C, A, b0_, b1_) \
    asm volatile("mma.sync.aligned.m16n8k16.row.col.f32.bf16.bf16.f32 " \
        "{%0,%1,%2,%3}, {%4,%5,%6,%7}, {%8,%9}, {%0,%1,%2,%3};" \
        : "+f"((C)[0]), "+f"((C)[1]), "+f"((C)[2]), "+f"((C)[3]) \
        : "r"((A)[0]), "r"((A)[1]), "r"((A)[2]), "r"((A)[3]), "r"(b0_), "r"(b1_))

// Dynamic smem layout.
#define OFF_C2   0                       // 1024 floats = 4096 B
#define OFF_Z2   4096                    // 128 floats
#define OFF_BK   4608                    // 128 ints
#define OFF_BUF0 8192                    // 3 planes x 16384 B (A first, then B odd panels)
#define OFF_BUF1 (OFF_BUF0 + 3 * 16384)  // 57344; B even panels
#define SMEM_TOTAL (OFF_BUF1 + 3 * 16384)   // 106496 B

static __device__ __forceinline__ void split3(float x, uint16_t& h, uint16_t& m, uint16_t& l) {
    __nv_bfloat16 bh = __float2bfloat16_rn(x);
    float r1 = x - __bfloat162float(bh);
    __nv_bfloat16 bm = __float2bfloat16_rn(r1);
    float r2 = r1 - __bfloat162float(bm);
    __nv_bfloat16 bl = __float2bfloat16_rn(r2);
    h = __bfloat16_as_ushort(bh);
    m = __bfloat16_as_ushort(bm);
    l = __bfloat16_as_ushort(bl);
}

// ---------------- prep: codebook split + c2 + scratch zero (warp/row) --------
// One warp per codebook row => 8 rows/block => needs GV*KV/8 = 1024 blocks.
__global__ void __launch_bounds__(256)
vq_prep_kernel(const float* __restrict__ cb) {
    int tid = threadIdx.x, lane = tid & 31, w = tid >> 5;
    int row = blockIdx.x * 8 + w;              // 0 .. 8191

    if (blockIdx.x < 4) g_hist[blockIdx.x * 256 + tid] = 0;
    if (blockIdx.x == 0 && tid == 0) g_commit = 0.0;

    const float2 v = ((const float2*)(cb + (size_t)row * DV))[lane];
    uint16_t h0, m0, l0, h1, m1, l1;
    split3(v.x, h0, m0, l0);
    split3(v.y, h1, m1, l1);
    size_t o = (size_t)row * DV + lane * 2;
    *(uint32_t*)&g_ch[o] = (uint32_t)h0 | ((uint32_t)h1 << 16);
    *(uint32_t*)&g_cm[o] = (uint32_t)m0 | ((uint32_t)m1 << 16);
    *(uint32_t*)&g_cl[o] = (uint32_t)l0 | ((uint32_t)l1 << 16);

    float s = fmaf(v.x, v.x, v.y * v.y);
#pragma unroll
    for (int off = 16; off > 0; off >>= 1)
        s += __shfl_down_sync(0xffffffffu, s, off);
    if (lane == 0) g_c2[row] = s;
}

__global__ void vq_nop_kernel() {}

// ---------------- main: mma.sync bf16x3 GEMM + fused argmin ----------------
__global__ void __launch_bounds__(256, 2)
vq_mma_kernel(const float* __restrict__ z,
              const float* __restrict__ cb,
              float* __restrict__ out) {
    extern __shared__ __align__(1024) char smem[];
    const int tid = threadIdx.x;
    const int w = tid >> 5, t = tid & 31;
    const int g = blockIdx.y;
    const int row0 = blockIdx.x * 128;

    uint32_t sb = (uint32_t)__cvta_generic_to_shared(smem);
    float* c2s = (float*)(smem + OFF_C2);
    float* z2s = (float*)(smem + OFF_Z2);
    int*   bks = (int*)(smem + OFF_BK);

    const uint16_t* cpl[3] = {g_ch, g_cm, g_cl};

    // B panel 0 -> BUF1 (overlaps with z prologue below).
#pragma unroll
    for (int it = 0; it < 12; it++) {
        int i = tid + 256 * it;
        int p = i >> 10, j = i & 1023, r = j >> 3, u = j & 7;
        const uint16_t* src = cpl[p] + (size_t)g * (KV * DV) + (size_t)r * DV + u * 8;
        cp_async16(sb + OFF_BUF1 + p * 16384 + r * 128 + ((u ^ (r & 7)) << 4), src);
    }
    cp_commit();

    // Stage c2 row for this group.
    *(float4*)&c2s[tid * 4] = *(const float4*)&g_c2[g * KV + tid * 4];

    // z tile: load fp32 coalesced, split in-register, store planes to BUF0.
    // 128 rows x 64 floats = 2048 float4 total -> 8 passes of 256 threads.
    {
        const float* zbase = z + (size_t)row0 * (GV * DV) + (size_t)g * DV;
#pragma unroll 4
        for (int pass = 0; pass < 8; pass++) {
            int f = tid + 256 * pass;           // float4 index 0..2047
            int r = f >> 4, u = f & 15;
            float4 v = __ldg((const float4*)(zbase + (size_t)r * (GV * DV) + u * 4));
            float vv[4] = {v.x, v.y, v.z, v.w};
            uint16_t hh[4], mm2[4], ll[4];
#pragma unroll
            for (int e = 0; e < 4; e++) split3(vv[e], hh[e], mm2[e], ll[e]);
            int ub = u >> 1;
            uint32_t byteoff = (uint32_t)(r * 128 + ((ub ^ (r & 7)) << 4) + (u & 1) * 8);
            uint2 ph = make_uint2((uint32_t)hh[0] | ((uint32_t)hh[1] << 16),
                                  (uint32_t)hh[2] | ((uint32_t)hh[3] << 16));
            uint2 pm = make_uint2((uint32_t)mm2[0] | ((uint32_t)mm2[1] << 16),
                                  (uint32_t)mm2[2] | ((uint32_t)mm2[3] << 16));
            uint2 pl = make_uint2((uint32_t)ll[0] | ((uint32_t)ll[1] << 16),
                                  (uint32_t)ll[2] | ((uint32_t)ll[3] << 16));
            *(uint2*)(smem + OFF_BUF0 + 0 * 16384 + byteoff) = ph;
            *(uint2*)(smem + OFF_BUF0 + 1 * 16384 + byteoff) = pm;
            *(uint2*)(smem + OFF_BUF0 + 2 * 16384 + byteoff) = pl;
        }
    }
    __syncthreads();    // A planes + c2s visible

    // A fragments from BUF0 (ldmatrix x4 lane mapping as in round 6).
    uint32_t af[3][4][4];
    {
        int rowoff = (t & 7) + ((t >> 3) & 1) * 8;
        int m = w * 16 + rowoff;
        int ub = (t >> 4) & 1;
#pragma unroll
        for (int p = 0; p < 3; p++)
#pragma unroll
            for (int ks = 0; ks < 4; ks++) {
                int u = ks * 2 + ub;
                uint32_t addr = sb + OFF_BUF0 + p * 16384 + m * 128 + ((u ^ (rowoff & 7)) << 4);
                LDSM_X4(af[p][ks], addr);
            }
    }

    // z2 per row from planes (constant offset per row -> argmin-safe rounding).
    if (tid < 128) {
        float s = 0.0f;
#pragma unroll
        for (int ub = 0; ub < 8; ub++) {
            uint32_t boff = (uint32_t)(tid * 128 + ((ub ^ (tid & 7)) << 4));
            uint4 H = *(uint4*)(smem + OFF_BUF0 + 0 * 16384 + boff);
            uint4 M = *(uint4*)(smem + OFF_BUF0 + 1 * 16384 + boff);
            uint4 L = *(uint4*)(smem + OFF_BUF0 + 2 * 16384 + boff);
            uint32_t hw[4] = {H.x, H.y, H.z, H.w};
            uint32_t mw[4] = {M.x, M.y, M.z, M.w};
            uint32_t lw[4] = {L.x, L.y, L.z, L.w};
#pragma unroll
            for (int q = 0; q < 4; q++) {
                float2 fh = __bfloat1622float2(*(__nv_bfloat162*)&hw[q]);
                float2 fm = __bfloat1622float2(*(__nv_bfloat162*)&mw[q]);
                float2 fl = __bfloat1622float2(*(__nv_bfloat162*)&lw[q]);
                float x0 = fh.x + fm.x + fl.x, x1 = fh.y + fm.y + fl.y;
                s = fmaf(x0, x0, s);
                s = fmaf(x1, x1, s);
            }
        }
        z2s[tid] = s;
    }

    float bestlo = 3.402823466e38f, besthi = 3.402823466e38f;
    int   klo = 0, khi = 0;
    float z2lo = 0.f, z2hi = 0.f;

    const int browoff = (t & 7) + ((t >> 4) & 1) * 8;
    const int bub = (t >> 3) & 1;
    const int j2 = (t & 3) * 2;

    for (int panel = 0; panel < 8; panel++) {
        cp_wait<0>();
        __syncthreads();    // panel data (and z2s on iter 0) visible; prior buffer free

        if (panel == 0) {
            z2lo = z2s[w * 16 + (t >> 2)];
            z2hi = z2s[w * 16 + (t >> 2) + 8];
        }

        if (panel < 7) {    // prefetch next panel into the other buffer
            uint32_t dstb = sb + (((panel + 1) & 1) ? OFF_BUF0 : OFF_BUF1);
#pragma unroll
            for (int it = 0; it < 12; it++) {
                int i = tid + 256 * it;
                int p = i >> 10, j = i & 1023, r = j >> 3, u = j & 7;
                const uint16_t* src = cpl[p] + (size_t)g * (KV * DV)
                                     + (size_t)((panel + 1) * 128 + r) * DV + u * 8;
                cp_async16(dstb + p * 16384 + r * 128 + ((u ^ (r & 7)) << 4), src);
            }
            cp_commit();
        }

        uint32_t bbase = sb + ((panel & 1) ? OFF_BUF0 : OFF_BUF1);
#pragma unroll 1
        for (int itn = 0; itn < 8; itn++) {
            float cA[4] = {0.f, 0.f, 0.f, 0.f};
            float cB[4] = {0.f, 0.f, 0.f, 0.f};
            int nloc = itn * 16;
            int br = nloc + browoff;
            uint32_t baddr0 = bbase + br * 128;
#pragma unroll
            for (int ks = 0; ks < 4; ks++) {
                uint32_t bb[3][4];
                int u = ks * 2 + bub;
                uint32_t sw = (uint32_t)((u ^ (br & 7)) << 4);
#pragma unroll
                for (int p = 0; p < 3; p++)
                    LDSM_X4(bb[p], baddr0 + p * 16384 + sw);
                MMA16816(cA, af[0][ks], bb[0][0], bb[0][1]);
                MMA16816(cB, af[0][ks], bb[0][2], bb[0][3]);
                MMA16816(cA, af[0][ks], bb[1][0], bb[1][1]);
                MMA16816(cB, af[0][ks], bb[1][2], bb[1][3]);
                MMA16816(cA, af[1][ks], bb[0][0], bb[0][1]);
                MMA16816(cB, af[1][ks], bb[0][2], bb[0][3]);
                MMA16816(cA, af[1][ks], bb[1][0], bb[1][1]);
                MMA16816(cB, af[1][ks], bb[1][2], bb[1][3]);
                MMA16816(cA, af[0][ks], bb[2][0], bb[2][1]);
                MMA16816(cB, af[0][ks], bb[2][2], bb[2][3]);
                MMA16816(cA, af[2][ks], bb[0][0], bb[0][1]);
                MMA16816(cB, af[2][ks], bb[0][2], bb[0][3]);
            }
            int kbase = panel * 128 + nloc;
            float2 p0 = *(const float2*)&c2s[kbase + j2];
            float2 p1 = *(const float2*)&c2s[kbase + 8 + j2];
            float d;
            d = fmaf(-2.0f, cA[0], z2lo + p0.x); if (d < bestlo) { bestlo = d; klo = kbase + j2; }
            d = fmaf(-2.0f, cA[1], z2lo + p0.y); if (d < bestlo) { bestlo = d; klo = kbase + j2 + 1; }
            d = fmaf(-2.0f, cB[0], z2lo + p1.x); if (d < bestlo) { bestlo = d; klo = kbase + 8 + j2; }
            d = fmaf(-2.0f, cB[1], z2lo + p1.y); if (d < bestlo) { bestlo = d; klo = kbase + 8 + j2 + 1; }
            d = fmaf(-2.0f, cA[2], z2hi + p0.x); if (d < besthi) { besthi = d; khi = kbase + j2; }
            d = fmaf(-2.0f, cA[3], z2hi + p0.y); if (d < besthi) { besthi = d; khi = kbase + j2 + 1; }
            d = fmaf(-2.0f, cB[2], z2hi + p1.x); if (d < besthi) { besthi = d; khi = kbase + 8 + j2; }
            d = fmaf(-2.0f, cB[3], z2hi + p1.y); if (d < besthi) { besthi = d; khi = kbase + 8 + j2 + 1; }
        }
    }

    // Cross-lane argmin within each quad (lexicographic: dist, then smaller k).
#pragma unroll
    for (int off = 1; off <= 2; off <<= 1) {
        float d2 = __shfl_xor_sync(0xffffffffu, bestlo, off);
        int   k2 = __shfl_xor_sync(0xffffffffu, klo, off);
        if (d2 < bestlo || (d2 == bestlo && k2 < klo)) { bestlo = d2; klo = k2; }
        d2 = __shfl_xor_sync(0xffffffffu, besthi, off);
        k2 = __shfl_xor_sync(0xffffffffu, khi, off);
        if (d2 < besthi || (d2 == besthi && k2 < khi)) { besthi = d2; khi = k2; }
    }
    if ((t & 3) == 0) {
        bks[w * 16 + (t >> 2)] = klo;
        bks[w * 16 + (t >> 2) + 8] = khi;
    }
    __syncthreads();

    // Cooperative output: thread handles half a row (32 floats).
    {
        int r = tid >> 1, half = tid & 1;
        int bk = bks[r];
        size_t brow = (size_t)(row0 + r);
        if (!half) {
            out[IDX_OFF + brow * GV + g] = (float)bk;
            atomicAdd(&g_hist[bk], 1);
        }
        const float4* q4 = (const float4*)(cb + (size_t)g * (KV * DV) + (size_t)bk * DV) + half * 8;
        const float4* z4 = (const float4*)(z + brow * (GV * DV) + (size_t)g * DV) + half * 8;
        float4* o4 = (float4*)(out + brow * (GV * DV) + (size_t)g * DV) + half * 8;
        float csum = 0.0f;
#pragma unroll
        for (int u = 0; u < 8; u++) {
            float4 q = q4[u], zv = z4[u];
            o4[u] = q;
            float d0 = zv.x - q.x, d1 = zv.y - q.y;
            float d2 = zv.z - q.z, d3 = zv.w - q.w;
            csum += d0 * d0 + d1 * d1 + d2 * d2 + d3 * d3;
        }
#pragma unroll
        for (int off = 16; off > 0; off >>= 1)
            csum += __shfl_down_sync(0xffffffffu, csum, off);
        float* red = z2s;   // z2s dead past the barrier above
        if (t == 0) red[w] = csum;
        __syncthreads();
        if (tid == 0) {
            float s = 0.0f;
#pragma unroll
            for (int i = 0; i < 8; i++) s += red[i];
            atomicAdd(&g_commit, (double)s);
        }
    }
}

// ---------------- final: entropy / perplexity / losses ----------------
__global__ void vq_final_kernel(float* __restrict__ out) {
    __shared__ float red[1024];
    int t = threadIdx.x;
    float u    = (float)g_hist[t] * (1.0f / (float)(BV * GV));
    float term = -u * logf(u + 1e-10f);
    red[t] = term;
    __syncthreads();
    for (int s = 512; s > 0; s >>= 1) {
        if (t < s) red[t] += red[t + s];
        __syncthreads();
    }
    if (t == 0) {
        float ent = red[0];
        out[SCL_OFF + 0] = (float)(g_commit / (double)Q_ELEMS);
        out[SCL_OFF + 1] = 0.0f;
        out[SCL_OFF + 2] = ent;
        out[SCL_OFF + 3] = expf(ent);
    }
}

extern "C" void kernel_launch(void* const* d_in, const int* in_sizes, int n_in,
                              void* d_out, int out_size) {
    const float* z  = (const float*)d_in[0];
    const float* cb = (const float*)d_in[1];
    if (n_in >= 2 && in_sizes[0] == GV * KV * DV) {
        cb = (const float*)d_in[0];
        z  = (const float*)d_in[1];
    }
    float* out = (float*)d_out;

    cudaFuncSetAttribute(vq_mma_kernel, cudaFuncAttributeMaxDynamicSharedMemorySize, SMEM_TOTAL);

    vq_prep_kernel<<<GV * KV / 8, 256>>>(cb);               // launch 1: 1024 blocks
    vq_nop_kernel<<<1, 32>>>();                             // launch 2
    vq_nop_kernel<<<1, 32>>>();                             // launch 3
    dim3 grid(BV / 128, GV);
    vq_mma_kernel<<<grid, 256, SMEM_TOTAL>>>(z, cb, out);   // launch 4 <- ncu capture slot
    vq_final_kernel<<<1, 1024>>>(out);                      // launch 5
}